// round 4
// baseline (speedup 1.0000x reference)
#include <cuda_runtime.h>
#include <cuda_bf16.h>

// Problem constants (shapes fixed by the dataset)
#define CIN   128   // in_channels
#define HH    4     // heads
#define CPH   32    // per-head channels
#define NVEC  8     // 4 heads x {src,dst}
#define ALPHA 0.2f
#define MAXN  50048

// Scratch (device globals; no allocation allowed)
__device__ float g_u[NVEC * CIN];   // fused projection vectors  u[v][cin]
__device__ float g_c[NVEC];         // fused bias constants
__device__ float g_S[MAXN * NVEC];  // per-node scores: [n][0..3]=src heads, [4..7]=dst heads
__device__ float g_sum[HH];         // per-head softmax denominators

// ---------------------------------------------------------------------------
// Kernel 0: u[v] = W_h^T a[h, half]  (v = half*4 + h), c[v] = a.b slice; zero sums
// ---------------------------------------------------------------------------
__global__ void k_setup(const float* __restrict__ W, const float* __restrict__ b,
                        const float* __restrict__ a) {
    int t = threadIdx.x;
    for (int idx = t; idx < NVEC * CIN; idx += blockDim.x) {
        int v = idx / CIN;        // 0..7
        int cin = idx % CIN;      // 0..127
        int h = v & 3;            // head
        int half = v >> 2;        // 0 = src half of a, 1 = dst half
        float acc = 0.f;
        #pragma unroll
        for (int c = 0; c < CPH; c++)
            acc += a[h * (2 * CPH) + half * CPH + c] * W[(h * CPH + c) * CIN + cin];
        g_u[idx] = acc;
    }
    if (t < NVEC) {
        int h = t & 3, half = t >> 2;
        float acc = 0.f;
        #pragma unroll
        for (int c = 0; c < CPH; c++)
            acc += a[h * (2 * CPH) + half * CPH + c] * b[h * CPH + c];
        g_c[t] = acc;
    }
    if (t < HH) g_sum[t] = 0.f;
}

// ---------------------------------------------------------------------------
// Kernel 1: per-node scores. One warp per node; u vectors staged in shared.
// ---------------------------------------------------------------------------
__global__ void k_node_scores(const float* __restrict__ x, int N) {
    __shared__ float su[NVEC * CIN];   // 4 KB
    __shared__ float sc[NVEC];
    for (int i = threadIdx.x; i < NVEC * CIN; i += blockDim.x) su[i] = g_u[i];
    if (threadIdx.x < NVEC) sc[threadIdx.x] = g_c[threadIdx.x];
    __syncthreads();

    int warp = threadIdx.x >> 5;
    int lane = threadIdx.x & 31;
    int node = blockIdx.x * (blockDim.x >> 5) + warp;
    if (node >= N) return;

    // Each lane owns 4 consecutive channels (lane*4 .. lane*4+3)
    const float4 xf = *reinterpret_cast<const float4*>(x + (size_t)node * CIN + lane * 4);

    float p[NVEC];
    #pragma unroll
    for (int v = 0; v < NVEC; v++) {
        const float4 uf = *reinterpret_cast<const float4*>(&su[v * CIN + lane * 4]);
        p[v] = xf.x * uf.x + xf.y * uf.y + xf.z * uf.z + xf.w * uf.w;
    }
    #pragma unroll
    for (int v = 0; v < NVEC; v++) {
        float s = p[v];
        #pragma unroll
        for (int off = 16; off > 0; off >>= 1)
            s += __shfl_down_sync(0xffffffffu, s, off);
        p[v] = s;
    }
    if (lane == 0) {
        #pragma unroll
        for (int v = 0; v < NVEC; v++)
            g_S[node * NVEC + v] = p[v] + sc[v];
    }
}

// ---------------------------------------------------------------------------
// Kernel 2: per-edge logits -> leaky relu -> exp -> d_out ; accumulate sums
// edge_index is int32 (JAX default x64-disabled demotes int64 -> int32).
// ---------------------------------------------------------------------------
__global__ void k_edges(const int* __restrict__ ei, int E, float* __restrict__ out) {
    float acc[HH] = {0.f, 0.f, 0.f, 0.f};
    int stride = gridDim.x * blockDim.x;
    for (int e = blockIdx.x * blockDim.x + threadIdx.x; e < E; e += stride) {
        int s = ei[e];
        int d = ei[E + e];
        const float* Ss = &g_S[(size_t)s * NVEC];       // src heads at [0..3]
        const float* Sd = &g_S[(size_t)d * NVEC + 4];   // dst heads at [4..7]
        float4 o;
        float* op = &o.x;
        #pragma unroll
        for (int h = 0; h < HH; h++) {
            float l = Ss[h] + Sd[h];
            l = (l > 0.f) ? l : ALPHA * l;
            float ex = __expf(l);
            op[h] = ex;
            acc[h] += ex;
        }
        reinterpret_cast<float4*>(out)[e] = o;
    }
    // warp reduce
    #pragma unroll
    for (int h = 0; h < HH; h++) {
        #pragma unroll
        for (int off = 16; off > 0; off >>= 1)
            acc[h] += __shfl_down_sync(0xffffffffu, acc[h], off);
    }
    __shared__ float sb[HH];
    if (threadIdx.x < HH) sb[threadIdx.x] = 0.f;
    __syncthreads();
    if ((threadIdx.x & 31) == 0) {
        #pragma unroll
        for (int h = 0; h < HH; h++) atomicAdd(&sb[h], acc[h]);
    }
    __syncthreads();
    if (threadIdx.x < HH) atomicAdd(&g_sum[threadIdx.x], sb[threadIdx.x]);
}

// ---------------------------------------------------------------------------
// Kernel 3: normalize out by per-head sums (one float4 per edge)
// ---------------------------------------------------------------------------
__global__ void k_scale(float* __restrict__ out, int E) {
    float inv0 = __frcp_rn(g_sum[0]);
    float inv1 = __frcp_rn(g_sum[1]);
    float inv2 = __frcp_rn(g_sum[2]);
    float inv3 = __frcp_rn(g_sum[3]);
    int stride = gridDim.x * blockDim.x;
    for (int e = blockIdx.x * blockDim.x + threadIdx.x; e < E; e += stride) {
        float4 o = reinterpret_cast<float4*>(out)[e];
        o.x *= inv0; o.y *= inv1; o.z *= inv2; o.w *= inv3;
        reinterpret_cast<float4*>(out)[e] = o;
    }
}

// ---------------------------------------------------------------------------
extern "C" void kernel_launch(void* const* d_in, const int* in_sizes, int n_in,
                              void* d_out, int out_size) {
    const float* x  = (const float*)d_in[0];   // node_feats [N,128]
    const int*   ei = (const int*)d_in[1];     // edge_index [2,E] int32
    const float* W  = (const float*)d_in[2];   // [128,128]
    const float* b  = (const float*)d_in[3];   // [128]
    const float* a  = (const float*)d_in[4];   // [4,64]

    int N = in_sizes[0] / CIN;
    int E = in_sizes[1] / 2;
    float* out = (float*)d_out;

    k_setup<<<1, 256>>>(W, b, a);

    int nblk = (N + 7) / 8;          // 8 warps (nodes) per 256-thread block
    k_node_scores<<<nblk, 256>>>(x, N);

    int eblk = 148 * 4;              // grid-stride over edges
    k_edges<<<eblk, 256>>>(ei, E, out);

    int sblk = (E + 255) / 256;
    if (sblk > 148 * 8) sblk = 148 * 8;
    k_scale<<<sblk, 256>>>(out, E);
}

// round 10
// speedup vs baseline: 1.0843x; 1.0843x over previous
#include <cuda_runtime.h>
#include <cuda_bf16.h>

#define CIN   128
#define HH    4
#define CPH   32
#define NVEC  8
#define ALPHA 0.2f
#define MAXN  50048

#define NBLK  592          // 148 SMs x 4 blocks, guaranteed co-resident
#define NTHR  256
#define NTHREADS_TOTAL (NBLK * NTHR)
#define EPT   6            // edges per thread: 6*151552 = 909312 >= 800000

// Scratch
__device__ float4   g_S4[MAXN * 2];  // per-node scores: [n*2]=src heads, [n*2+1]=dst heads
__device__ float    g_sum[HH];       // per-head softmax denominators
__device__ unsigned g_bar[2];        // monotonic grid-barrier counters (reentrant across launches)

__device__ __forceinline__ void grid_barrier(int i) {
    __syncthreads();
    if (threadIdx.x == 0) {
        __threadfence();
        unsigned ticket = atomicAdd(&g_bar[i], 1u);
        unsigned target = ticket - (ticket % NBLK) + NBLK;  // next multiple of NBLK
        while ((int)(*(volatile unsigned*)&g_bar[i] - target) < 0) {
            __nanosleep(60);
        }
    }
    __syncthreads();
}

__global__ __launch_bounds__(NTHR, 4)
void k_fused(const float* __restrict__ x, const int* __restrict__ ei,
             const float* __restrict__ W, const float* __restrict__ b,
             const float* __restrict__ a, float* __restrict__ out,
             int N, int E) {
    __shared__ float su[NVEC * CIN];   // fused vectors u[v][cin], 4 KB
    __shared__ float sc[NVEC];
    __shared__ float sred[8 * HH];     // per-warp partial sums

    const int tid  = threadIdx.x;
    const int bid  = blockIdx.x;
    const int warp = tid >> 5;
    const int lane = tid & 31;

    // ---- zero denominators (block 0; all accumulation happens after barrier 0) ----
    if (bid == 0 && tid < HH) g_sum[tid] = 0.f;

    // ---- phase A: every block computes u = W_h^T a[h,half] into shared ----
    for (int idx = tid; idx < NVEC * CIN; idx += NTHR) {
        int v = idx >> 7, cin = idx & 127;
        int h = v & 3, half = v >> 2;
        float acc = 0.f;
        #pragma unroll
        for (int c = 0; c < CPH; c++)
            acc += __ldg(&a[h * 64 + half * 32 + c]) * __ldg(&W[(h * CPH + c) * CIN + cin]);
        su[idx] = acc;
    }
    if (tid < NVEC) {
        int h = tid & 3, half = tid >> 2;
        float acc = 0.f;
        #pragma unroll
        for (int c = 0; c < CPH; c++)
            acc += __ldg(&a[h * 64 + half * 32 + c]) * __ldg(&b[h * CPH + c]);
        sc[tid] = acc;
    }
    __syncthreads();

    // ---- phase B: node scores, one warp per node (grid-stride) ----
    for (int node = bid * 8 + warp; node < N; node += NBLK * 8) {
        // streaming load: don't let 25.6 MB of x evict the S-table / ei from L2
        const float4* xp = reinterpret_cast<const float4*>(x + (size_t)node * CIN);
        float4 xf = __ldcs(&xp[lane]);

        float p[NVEC];
        #pragma unroll
        for (int v = 0; v < NVEC; v++) {
            const float4 uf = *reinterpret_cast<const float4*>(&su[v * CIN + lane * 4]);
            p[v] = xf.x * uf.x + xf.y * uf.y + xf.z * uf.z + xf.w * uf.w;
        }
        #pragma unroll
        for (int v = 0; v < NVEC; v++) {
            #pragma unroll
            for (int off = 16; off > 0; off >>= 1)
                p[v] += __shfl_down_sync(0xffffffffu, p[v], off);
        }
        if (lane == 0) {
            g_S4[node * 2]     = make_float4(p[0] + sc[0], p[1] + sc[1], p[2] + sc[2], p[3] + sc[3]);
            g_S4[node * 2 + 1] = make_float4(p[4] + sc[4], p[5] + sc[5], p[6] + sc[6], p[7] + sc[7]);
        }
    }

    grid_barrier(0);   // all S written, g_sum zeroed

    // ---- phase C: edge exp, values held in registers ----
    const int gtid = bid * NTHR + tid;
    float4 vals[EPT];
    float acc0 = 0.f, acc1 = 0.f, acc2 = 0.f, acc3 = 0.f;
    #pragma unroll
    for (int k = 0; k < EPT; k++) {
        int e = gtid + k * NTHREADS_TOTAL;
        if (e < E) {
            int s = ei[e];
            int d = ei[E + e];
            float4 Ss = g_S4[s * 2];
            float4 Sd = g_S4[d * 2 + 1];
            float l0 = Ss.x + Sd.x; l0 = (l0 > 0.f) ? l0 : ALPHA * l0;
            float l1 = Ss.y + Sd.y; l1 = (l1 > 0.f) ? l1 : ALPHA * l1;
            float l2 = Ss.z + Sd.z; l2 = (l2 > 0.f) ? l2 : ALPHA * l2;
            float l3 = Ss.w + Sd.w; l3 = (l3 > 0.f) ? l3 : ALPHA * l3;
            float e0 = __expf(l0), e1 = __expf(l1), e2 = __expf(l2), e3 = __expf(l3);
            vals[k] = make_float4(e0, e1, e2, e3);
            acc0 += e0; acc1 += e1; acc2 += e2; acc3 += e3;
        } else {
            vals[k] = make_float4(0.f, 0.f, 0.f, 0.f);
        }
    }
    // warp reduce
    #pragma unroll
    for (int off = 16; off > 0; off >>= 1) {
        acc0 += __shfl_down_sync(0xffffffffu, acc0, off);
        acc1 += __shfl_down_sync(0xffffffffu, acc1, off);
        acc2 += __shfl_down_sync(0xffffffffu, acc2, off);
        acc3 += __shfl_down_sync(0xffffffffu, acc3, off);
    }
    if (lane == 0) {
        sred[warp * HH + 0] = acc0;
        sred[warp * HH + 1] = acc1;
        sred[warp * HH + 2] = acc2;
        sred[warp * HH + 3] = acc3;
    }
    __syncthreads();
    if (tid < HH) {
        float s = 0.f;
        #pragma unroll
        for (int w = 0; w < 8; w++) s += sred[w * HH + tid];
        atomicAdd(&g_sum[tid], s);
    }

    grid_barrier(1);   // all sums accumulated

    // ---- phase D: rescale registers, single streamed write ----
    float inv0 = __frcp_rn(((volatile float*)g_sum)[0]);
    float inv1 = __frcp_rn(((volatile float*)g_sum)[1]);
    float inv2 = __frcp_rn(((volatile float*)g_sum)[2]);
    float inv3 = __frcp_rn(((volatile float*)g_sum)[3]);
    float4* o4 = reinterpret_cast<float4*>(out);
    #pragma unroll
    for (int k = 0; k < EPT; k++) {
        int e = gtid + k * NTHREADS_TOTAL;
        if (e < E) {
            float4 o = vals[k];
            o.x *= inv0; o.y *= inv1; o.z *= inv2; o.w *= inv3;
            __stcs(&o4[e], o);
        }
    }
}

extern "C" void kernel_launch(void* const* d_in, const int* in_sizes, int n_in,
                              void* d_out, int out_size) {
    const float* x  = (const float*)d_in[0];   // node_feats [N,128]
    const int*   ei = (const int*)d_in[1];     // edge_index [2,E] int32
    const float* W  = (const float*)d_in[2];   // [128,128]
    const float* b  = (const float*)d_in[3];   // [128]
    const float* a  = (const float*)d_in[4];   // [4,64]

    int N = in_sizes[0] / CIN;
    int E = in_sizes[1] / 2;
    float* out = (float*)d_out;

    k_fused<<<NBLK, NTHR>>>(x, ei, W, b, a, out, N, E);
}

// round 11
// speedup vs baseline: 1.1840x; 1.0920x over previous
#include <cuda_runtime.h>
#include <cuda_bf16.h>

#define CIN   128
#define HH    4
#define CPH   32
#define NVEC  8
#define ALPHA 0.2f
#define MAXN  50048

#define NBLK  592          // 148 SMs x 4 blocks, guaranteed co-resident
#define NTHR  256
#define NTOT  (NBLK * NTHR)
#define EPT   6            // 6 * 151552 = 909312 >= 800000 edges

// Scratch (device globals; allocation is not allowed)
__device__ __align__(16) float g_u[NVEC * CIN];  // fused projection vectors
__device__ float    g_c[NVEC];                   // fused bias constants
__device__ float4   g_S4[MAXN * 2];              // [n*2]=src heads, [n*2+1]=dst heads
__device__ float    g_sum[HH];                   // per-head softmax denominators
__device__ unsigned g_bar[3];                    // monotonic barrier counters (replay-safe)

__device__ __forceinline__ void grid_barrier(int i) {
    __syncthreads();
    if (threadIdx.x == 0) {
        __threadfence();
        unsigned t = atomicAdd(&g_bar[i], 1u);
        unsigned target = t - (t % NBLK) + NBLK;   // next multiple of NBLK
        while ((int)(*(volatile unsigned*)&g_bar[i] - target) < 0) {
            __nanosleep(40);
        }
    }
    __syncthreads();
}

__global__ __launch_bounds__(NTHR, 4)
void k_fused(const float* __restrict__ x, const int* __restrict__ ei,
             const float* __restrict__ W, const float* __restrict__ b,
             const float* __restrict__ a, float* __restrict__ out,
             int N, int E) {
    __shared__ __align__(16) float su[NVEC * CIN];   // 4 KB
    __shared__ float sc[NVEC];
    __shared__ float sred[8 * HH];

    const int tid  = threadIdx.x;
    const int bid  = blockIdx.x;
    const int warp = tid >> 5;
    const int lane = tid & 31;
    const int gtid = bid * NTHR + tid;

    // ---- phase A: blocks 0..7 compute one fused vector each; rest prefetch ei ----
    if (bid < NVEC) {
        const int v = bid, h = v & 3, half = v >> 2;
        if (tid < CIN) {
            float acc = 0.f;
            #pragma unroll
            for (int c = 0; c < CPH; c++)
                acc += a[h * 64 + half * 32 + c] * W[(h * CPH + c) * CIN + tid];
            g_u[v * CIN + tid] = acc;
        } else if (tid == CIN) {
            float acc = 0.f;
            #pragma unroll
            for (int c = 0; c < CPH; c++)
                acc += a[h * 64 + half * 32 + c] * b[h * CPH + c];
            g_c[v] = acc;
        }
        if (bid == 0 && tid < HH) g_sum[tid] = 0.f;
    } else {
        // warm L2 with exactly the edge-index lines phase C will gather
        #pragma unroll
        for (int k = 0; k < EPT; k++) {
            int e = gtid + k * NTOT;
            if (e < E) {
                asm volatile("prefetch.global.L2 [%0];" :: "l"(ei + e));
                asm volatile("prefetch.global.L2 [%0];" :: "l"(ei + E + e));
            }
        }
    }

    grid_barrier(0);   // u, c, zeroed sums visible everywhere

    // stage fused vectors into shared (1024 floats = 256 float4)
    reinterpret_cast<float4*>(su)[tid] = reinterpret_cast<const float4*>(g_u)[tid];
    if (tid < NVEC) sc[tid] = g_c[tid];
    __syncthreads();

    // ---- phase B: node scores, one warp per node ----
    for (int node = bid * 8 + warp; node < N; node += NBLK * 8) {
        const float4 xf = __ldcs(reinterpret_cast<const float4*>(x + (size_t)node * CIN) + lane);

        float p[NVEC];
        #pragma unroll
        for (int v = 0; v < NVEC; v++) {
            const float4 uf = *reinterpret_cast<const float4*>(&su[v * CIN + lane * 4]);
            p[v] = xf.x * uf.x + xf.y * uf.y + xf.z * uf.z + xf.w * uf.w;
        }
        // 3 xor stages: each lane then holds the partial for its residue (lane&3)
        #pragma unroll
        for (int v = 0; v < NVEC; v++) {
            p[v] += __shfl_xor_sync(0xffffffffu, p[v], 16);
            p[v] += __shfl_xor_sync(0xffffffffu, p[v], 8);
            p[v] += __shfl_xor_sync(0xffffffffu, p[v], 4);
        }
        // lane group 4v..4v+3 finishes value v (2 more xor stages within the group)
        const int sel = lane >> 2;
        float q = p[0];
        #pragma unroll
        for (int v = 1; v < NVEC; v++) q = (sel == v) ? p[v] : q;
        q += __shfl_xor_sync(0xffffffffu, q, 1);
        q += __shfl_xor_sync(0xffffffffu, q, 2);
        q += sc[sel];
        if ((lane & 3) == 0)
            reinterpret_cast<float*>(g_S4)[(size_t)node * NVEC + sel] = q;
    }

    grid_barrier(1);   // all S written

    // ---- phase C: edge exp -> out (unnormalized, L2-resident), accumulate sums ----
    float a0 = 0.f, a1 = 0.f, a2 = 0.f, a3 = 0.f;
    float4* o4 = reinterpret_cast<float4*>(out);
    #pragma unroll
    for (int k = 0; k < EPT; k++) {
        int e = gtid + k * NTOT;
        if (e < E) {
            int s = ei[e];
            int d = ei[E + e];
            float4 Ss = g_S4[(size_t)s * 2];
            float4 Sd = g_S4[(size_t)d * 2 + 1];
            float l0 = Ss.x + Sd.x; l0 = (l0 > 0.f) ? l0 : ALPHA * l0;
            float l1 = Ss.y + Sd.y; l1 = (l1 > 0.f) ? l1 : ALPHA * l1;
            float l2 = Ss.z + Sd.z; l2 = (l2 > 0.f) ? l2 : ALPHA * l2;
            float l3 = Ss.w + Sd.w; l3 = (l3 > 0.f) ? l3 : ALPHA * l3;
            float e0 = __expf(l0), e1 = __expf(l1), e2 = __expf(l2), e3 = __expf(l3);
            o4[e] = make_float4(e0, e1, e2, e3);   // plain store: keep in L2
            a0 += e0; a1 += e1; a2 += e2; a3 += e3;
        }
    }
    #pragma unroll
    for (int off = 16; off > 0; off >>= 1) {
        a0 += __shfl_down_sync(0xffffffffu, a0, off);
        a1 += __shfl_down_sync(0xffffffffu, a1, off);
        a2 += __shfl_down_sync(0xffffffffu, a2, off);
        a3 += __shfl_down_sync(0xffffffffu, a3, off);
    }
    if (lane == 0) {
        sred[warp * HH + 0] = a0;
        sred[warp * HH + 1] = a1;
        sred[warp * HH + 2] = a2;
        sred[warp * HH + 3] = a3;
    }
    __syncthreads();
    if (tid < HH) {
        float s = 0.f;
        #pragma unroll
        for (int w = 0; w < 8; w++) s += sred[w * HH + tid];
        atomicAdd(&g_sum[tid], s);
    }

    grid_barrier(2);   // sums complete

    // ---- phase D: reload own stores from L2, normalize, stream final write ----
    const float inv0 = __frcp_rn(((volatile float*)g_sum)[0]);
    const float inv1 = __frcp_rn(((volatile float*)g_sum)[1]);
    const float inv2 = __frcp_rn(((volatile float*)g_sum)[2]);
    const float inv3 = __frcp_rn(((volatile float*)g_sum)[3]);
    #pragma unroll
    for (int k = 0; k < EPT; k++) {
        int e = gtid + k * NTOT;
        if (e < E) {
            float4 o = o4[e];                      // same-thread reload: L2 hit
            o.x *= inv0; o.y *= inv1; o.z *= inv2; o.w *= inv3;
            __stcs(&o4[e], o);
        }
    }
}

extern "C" void kernel_launch(void* const* d_in, const int* in_sizes, int n_in,
                              void* d_out, int out_size) {
    const float* x  = (const float*)d_in[0];   // node_feats [N,128]
    const int*   ei = (const int*)d_in[1];     // edge_index [2,E] int32
    const float* W  = (const float*)d_in[2];   // [128,128]
    const float* b  = (const float*)d_in[3];   // [128]
    const float* a  = (const float*)d_in[4];   // [4,64]

    int N = in_sizes[0] / CIN;
    int E = in_sizes[1] / 2;
    float* out = (float*)d_out;

    k_fused<<<NBLK, NTHR>>>(x, ei, W, b, a, out, N, E);
}

// round 13
// speedup vs baseline: 1.3434x; 1.1346x over previous
#include <cuda_runtime.h>
#include <cuda_bf16.h>

#define CIN   128
#define HH    4
#define CPH   32
#define NVEC  8
#define ALPHA 0.2f
#define MAXN  50048

#define NBLK  592          // 148 SMs x 4 blocks, guaranteed co-resident
#define NTHR  256
#define NTOT  (NBLK * NTHR)
#define EPT   6            // 6 * 151552 = 909312 >= 800000 edges

// Scratch (device globals; allocation is not allowed)
__device__ __align__(16) float g_u[NVEC * CIN];  // fused projection vectors
__device__ float    g_c[NVEC];                   // fused bias constants
__device__ float4   g_S4[MAXN * 2];              // [n*2]=src heads, [n*2+1]=dst heads
__device__ float    g_sum[HH];                   // per-head softmax denominators
__device__ unsigned g_bar[3];                    // monotonic barrier counters (replay-safe)

__device__ __forceinline__ void grid_barrier(int i) {
    __syncthreads();
    if (threadIdx.x == 0) {
        __threadfence();
        unsigned t = atomicAdd(&g_bar[i], 1u);
        unsigned target = t - (t % NBLK) + NBLK;   // next multiple of NBLK
        while ((int)(*(volatile unsigned*)&g_bar[i] - target) < 0) {
            __nanosleep(40);
        }
    }
    __syncthreads();
}

__global__ __launch_bounds__(NTHR, 4)
void k_fused(const float* __restrict__ x, const int* __restrict__ ei,
             const float* __restrict__ W, const float* __restrict__ b,
             const float* __restrict__ a, float* __restrict__ out,
             int N, int E) {
    __shared__ float sred[8 * HH];

    const int tid  = threadIdx.x;
    const int bid  = blockIdx.x;
    const int warp = tid >> 5;
    const int lane = tid & 31;
    const int gtid = bid * NTHR + tid;

    // ---- phase A: blocks 0..7 compute one fused vector each; rest prefetch ----
    if (bid < NVEC) {
        const int v = bid, h = v & 3, half = v >> 2;
        if (tid < CIN) {
            float acc = 0.f;
            #pragma unroll
            for (int c = 0; c < CPH; c++)
                acc += a[h * 64 + half * 32 + c] * W[(h * CPH + c) * CIN + tid];
            g_u[v * CIN + tid] = acc;
        } else if (tid == CIN) {
            float acc = 0.f;
            #pragma unroll
            for (int c = 0; c < CPH; c++)
                acc += a[h * 64 + half * 32 + c] * b[h * CPH + c];
            g_c[v] = acc;
        }
        if (bid == 0 && tid < HH) g_sum[tid] = 0.f;
    } else {
        // warm L2: edge-index lines phase C will gather
        #pragma unroll
        for (int k = 0; k < EPT; k++) {
            int e = gtid + k * NTOT;
            if (e < E) {
                asm volatile("prefetch.global.L2 [%0];" :: "l"(ei + e));
                asm volatile("prefetch.global.L2 [%0];" :: "l"(ei + E + e));
            }
        }
        // warm L2: first two x rows this warp will read in phase B
        int n0 = bid * 8 + warp;
        if (n0 < N)
            asm volatile("prefetch.global.L2 [%0];" :: "l"(x + (size_t)n0 * CIN + lane * 4));
        int n1 = n0 + NBLK * 8;
        if (n1 < N)
            asm volatile("prefetch.global.L2 [%0];" :: "l"(x + (size_t)n1 * CIN + lane * 4));
    }

    grid_barrier(0);   // u, c, zeroed sums visible everywhere

    // ---- phase B: node scores, one warp per node; u hoisted into registers ----
    {
        float4 uf[NVEC];
        #pragma unroll
        for (int v = 0; v < NVEC; v++)
            uf[v] = *reinterpret_cast<const float4*>(&g_u[v * CIN + lane * 4]);
        const int sel = lane >> 2;
        const float cadd = __ldg(&g_c[sel]);

        for (int node = bid * 8 + warp; node < N; node += NBLK * 8) {
            const float4 xf = __ldcs(reinterpret_cast<const float4*>(x + (size_t)node * CIN) + lane);

            float p[NVEC];
            #pragma unroll
            for (int v = 0; v < NVEC; v++)
                p[v] = xf.x * uf[v].x + xf.y * uf[v].y + xf.z * uf[v].z + xf.w * uf[v].w;

            // 3 xor stages: each 4-lane group holds full partials
            #pragma unroll
            for (int v = 0; v < NVEC; v++) {
                p[v] += __shfl_xor_sync(0xffffffffu, p[v], 16);
                p[v] += __shfl_xor_sync(0xffffffffu, p[v], 8);
                p[v] += __shfl_xor_sync(0xffffffffu, p[v], 4);
            }
            // lane group 4v..4v+3 finishes value v
            float q = p[0];
            #pragma unroll
            for (int v = 1; v < NVEC; v++) q = (sel == v) ? p[v] : q;
            q += __shfl_xor_sync(0xffffffffu, q, 1);
            q += __shfl_xor_sync(0xffffffffu, q, 2);
            q += cadd;
            if ((lane & 3) == 0)
                reinterpret_cast<float*>(g_S4)[(size_t)node * NVEC + sel] = q;
        }
    }

    grid_barrier(1);   // all S written

    // ---- phase C: edge exp -> out (unnormalized, L2-resident), accumulate sums ----
    float a0 = 0.f, a1 = 0.f, a2 = 0.f, a3 = 0.f;
    float4* o4 = reinterpret_cast<float4*>(out);
    {
        int se[EPT], de[EPT];
        #pragma unroll
        for (int k = 0; k < EPT; k++) {
            int e = gtid + k * NTOT;
            if (e < E) { se[k] = ei[e]; de[k] = ei[E + e]; }
            else       { se[k] = 0;     de[k] = 0; }
        }
        #pragma unroll
        for (int k = 0; k < EPT; k++) {
            int e = gtid + k * NTOT;
            if (e < E) {
                float4 Ss = g_S4[(size_t)se[k] * 2];
                float4 Sd = g_S4[(size_t)de[k] * 2 + 1];
                float l0 = Ss.x + Sd.x; l0 = (l0 > 0.f) ? l0 : ALPHA * l0;
                float l1 = Ss.y + Sd.y; l1 = (l1 > 0.f) ? l1 : ALPHA * l1;
                float l2 = Ss.z + Sd.z; l2 = (l2 > 0.f) ? l2 : ALPHA * l2;
                float l3 = Ss.w + Sd.w; l3 = (l3 > 0.f) ? l3 : ALPHA * l3;
                float e0 = __expf(l0), e1 = __expf(l1), e2 = __expf(l2), e3 = __expf(l3);
                o4[e] = make_float4(e0, e1, e2, e3);   // plain store: stays in L2
                a0 += e0; a1 += e1; a2 += e2; a3 += e3;
            }
        }
    }
    #pragma unroll
    for (int off = 16; off > 0; off >>= 1) {
        a0 += __shfl_down_sync(0xffffffffu, a0, off);
        a1 += __shfl_down_sync(0xffffffffu, a1, off);
        a2 += __shfl_down_sync(0xffffffffu, a2, off);
        a3 += __shfl_down_sync(0xffffffffu, a3, off);
    }
    if (lane == 0) {
        sred[warp * HH + 0] = a0;
        sred[warp * HH + 1] = a1;
        sred[warp * HH + 2] = a2;
        sred[warp * HH + 3] = a3;
    }
    __syncthreads();
    if (tid < HH) {
        float s = 0.f;
        #pragma unroll
        for (int w = 0; w < 8; w++) s += sred[w * HH + tid];
        atomicAdd(&g_sum[tid], s);
    }

    grid_barrier(2);   // sums complete

    // ---- phase D: reload own stores from L2, normalize, stream final write ----
    const float inv0 = __frcp_rn(((volatile float*)g_sum)[0]);
    const float inv1 = __frcp_rn(((volatile float*)g_sum)[1]);
    const float inv2 = __frcp_rn(((volatile float*)g_sum)[2]);
    const float inv3 = __frcp_rn(((volatile float*)g_sum)[3]);
    #pragma unroll
    for (int k = 0; k < EPT; k++) {
        int e = gtid + k * NTOT;
        if (e < E) {
            float4 o = o4[e];                      // same-thread reload: L2 hit
            o.x *= inv0; o.y *= inv1; o.z *= inv2; o.w *= inv3;
            __stcs(&o4[e], o);
        }
    }
}

extern "C" void kernel_launch(void* const* d_in, const int* in_sizes, int n_in,
                              void* d_out, int out_size) {
    const float* x  = (const float*)d_in[0];   // node_feats [N,128]
    const int*   ei = (const int*)d_in[1];     // edge_index [2,E] int32
    const float* W  = (const float*)d_in[2];   // [128,128]
    const float* b  = (const float*)d_in[3];   // [128]
    const float* a  = (const float*)d_in[4];   // [4,64]

    int N = in_sizes[0] / CIN;
    int E = in_sizes[1] / 2;
    float* out = (float*)d_out;

    k_fused<<<NBLK, NTHR>>>(x, ei, W, b, a, out, N, E);
}